// round 4
// baseline (speedup 1.0000x reference)
#include <cuda_runtime.h>
#include <cstdint>

// ============================================================================
// LoRADense: out = x @ W + bias + (x . A[id]) . B[id]
//   x: (8192,1024) f32   adapter_ids: (8192,) i32   W: (1024,1024) f32
//   bias: (1024,) f32    lora_a: (64,1024,16) f32   lora_b: (64,16,1024) f32
//
// sm_100 plain target => no tcgen05. Classic mma.sync m16n8k8 tf32:
//   1) transpose W -> g_wt (F,D), tf32 rna-rounded (bit pattern in b32)
//   2) pipelined tf32 GEMM: BM=256 BN=128 BK=32, 3-stage cp.async, 512 thr
//   3) grouped LoRA: 2 CTAs per adapter, A/B in SMEM, warp-per-token RMW
// ============================================================================

#define N_TOK 8192
#define DIM   1024
#define FEAT  1024

__device__ float g_wt[FEAT * DIM];   // W^T, tf32-rounded (4 MB scratch)

// tf32 destination must be a .b32 register in PTX
__device__ __forceinline__ uint32_t to_tf32(float v) {
    uint32_t o;
    asm("cvt.rna.tf32.f32 %0, %1;" : "=r"(o) : "f"(v));
    return o;
}
__device__ __forceinline__ void cp16(uint32_t dst, const void* src) {
    asm volatile("cp.async.cg.shared.global [%0], [%1], 16;" :: "r"(dst), "l"(src));
}
__device__ __forceinline__ uint32_t smem_u32(const void* p) {
    uint32_t a;
    asm("{ .reg .u64 t; cvta.to.shared.u64 t, %1; cvt.u32.u64 %0, t; }"
        : "=r"(a) : "l"(p));
    return a;
}
__device__ __forceinline__ void mma_tf32(float& c0, float& c1, float& c2, float& c3,
                                         uint32_t a0, uint32_t a1, uint32_t a2, uint32_t a3,
                                         uint32_t b0, uint32_t b1) {
    asm volatile(
        "mma.sync.aligned.m16n8k8.row.col.f32.tf32.tf32.f32 "
        "{%0,%1,%2,%3}, {%4,%5,%6,%7}, {%8,%9}, {%0,%1,%2,%3};"
        : "+f"(c0), "+f"(c1), "+f"(c2), "+f"(c3)
        : "r"(a0), "r"(a1), "r"(a2), "r"(a3), "r"(b0), "r"(b1));
}

// ============================================================================
// Kernel 1: W (D,F) -> g_wt (F,D), tf32-rounded
// ============================================================================
__global__ void transpose_w_kernel(const float* __restrict__ W) {
    __shared__ float t[32][33];
    int fx = blockIdx.x * 32 + threadIdx.x;
    int dy = blockIdx.y * 32 + threadIdx.y;
#pragma unroll
    for (int i = 0; i < 32; i += 8)
        t[threadIdx.y + i][threadIdx.x] = W[(size_t)(dy + i) * FEAT + fx];
    __syncthreads();
    int dx = blockIdx.y * 32 + threadIdx.x;
    int fy = blockIdx.x * 32 + threadIdx.y;
#pragma unroll
    for (int i = 0; i < 32; i += 8)
        g_wt[(size_t)(fy + i) * DIM + dx] =
            __uint_as_float(to_tf32(t[threadIdx.x][threadIdx.y + i]));
}

// ============================================================================
// Kernel 2: tf32 GEMM via mma.sync m16n8k8
//   BM=256 BN=128 BK=32, 512 threads (16 warps, 8x2), warp tile 32x64
// ============================================================================
static constexpr int BM = 256, BN = 128, BK = 32;
static constexpr int AS = 36;                     // padded row stride (floats)
static constexpr int NKCH = DIM / BK;             // 32
static constexpr int DEPTH = 3;
static constexpr int A_FLOATS = BM * AS;          // 9216
static constexpr int B_FLOATS = BN * AS;          // 4608
static constexpr int STAGE_FLOATS = A_FLOATS + B_FLOATS;
static constexpr int GEMM_SMEM = DEPTH * STAGE_FLOATS * 4;   // 165888 B

__device__ __forceinline__ void load_stage(uint32_t sb, int slot, int kc,
                                           const float* __restrict__ x,
                                           int mbase, int nbase, int tid) {
    uint32_t baseA = sb + (uint32_t)(slot * STAGE_FLOATS) * 4u;
    uint32_t baseB = baseA + (uint32_t)A_FLOATS * 4u;
    const float* xp = x    + (size_t)mbase * DIM + kc * BK;
    const float* wp = g_wt + (size_t)nbase * DIM + kc * BK;
    // A: 256 rows x 8 16B-chunks = 2048 chunks, 4 per thread
#pragma unroll
    for (int it = 0; it < 4; it++) {
        int c  = tid + it * 512;
        int r  = c >> 3, cc = c & 7;
        cp16(baseA + (uint32_t)(r * AS + cc * 4) * 4u, xp + (size_t)r * DIM + cc * 4);
    }
    // B: 128 rows x 8 chunks = 1024 chunks, 2 per thread
#pragma unroll
    for (int it = 0; it < 2; it++) {
        int c  = tid + it * 512;
        int r  = c >> 3, cc = c & 7;
        cp16(baseB + (uint32_t)(r * AS + cc * 4) * 4u, wp + (size_t)r * DIM + cc * 4);
    }
}

__global__ void __launch_bounds__(512, 1)
gemm_tf32_kernel(const float* __restrict__ x, const float* __restrict__ bias,
                 float* __restrict__ out) {
    extern __shared__ float smem[];
    uint32_t sb = smem_u32(smem);

    const int tid = threadIdx.x;
    const int wid = tid >> 5, lane = tid & 31;
    const int wm = wid >> 1, wn = wid & 1;     // 8 x 2 warp grid
    const int qr = lane >> 2, qc = lane & 3;
    const int mbase = blockIdx.x * BM;
    const int nbase = blockIdx.y * BN;

    float acc[2][8][4];
#pragma unroll
    for (int mi = 0; mi < 2; mi++)
#pragma unroll
        for (int ni = 0; ni < 8; ni++)
#pragma unroll
            for (int q = 0; q < 4; q++) acc[mi][ni][q] = 0.f;

    // prologue: chunks 0,1 -> slots 0,1
    load_stage(sb, 0, 0, x, mbase, nbase, tid);
    asm volatile("cp.async.commit_group;" ::: "memory");
    load_stage(sb, 1, 1, x, mbase, nbase, tid);
    asm volatile("cp.async.commit_group;" ::: "memory");

#pragma unroll 1
    for (int i = 0; i < NKCH; i++) {
        if (i >= NKCH - 1) asm volatile("cp.async.wait_group 0;" ::: "memory");
        else               asm volatile("cp.async.wait_group 1;" ::: "memory");
        __syncthreads();   // chunk i landed; all warps done with chunk i-1

        if (i + 2 < NKCH) {
            load_stage(sb, (i + 2) % DEPTH, i + 2, x, mbase, nbase, tid);
            asm volatile("cp.async.commit_group;" ::: "memory");
        }

        const int slot = i % DEPTH;
        const uint32_t* As = (const uint32_t*)(smem + slot * STAGE_FLOATS);
        const uint32_t* Bs = As + A_FLOATS;

#pragma unroll
        for (int ks = 0; ks < 4; ks++) {
            const int kb = ks * 8;
            uint32_t a[2][4];
#pragma unroll
            for (int mi = 0; mi < 2; mi++) {
                int row = wm * 32 + mi * 16 + qr;
                a[mi][0] = As[row * AS + kb + qc];
                a[mi][1] = As[(row + 8) * AS + kb + qc];
                a[mi][2] = As[row * AS + kb + qc + 4];
                a[mi][3] = As[(row + 8) * AS + kb + qc + 4];
            }
            uint32_t b[8][2];
#pragma unroll
            for (int ni = 0; ni < 8; ni++) {
                int col = wn * 64 + ni * 8 + qr;
                b[ni][0] = Bs[col * AS + kb + qc];
                b[ni][1] = Bs[col * AS + kb + qc + 4];
            }
#pragma unroll
            for (int mi = 0; mi < 2; mi++)
#pragma unroll
                for (int ni = 0; ni < 8; ni++)
                    mma_tf32(acc[mi][ni][0], acc[mi][ni][1],
                             acc[mi][ni][2], acc[mi][ni][3],
                             a[mi][0], a[mi][1], a[mi][2], a[mi][3],
                             b[ni][0], b[ni][1]);
        }
    }

    // epilogue: out = acc + bias
#pragma unroll
    for (int mi = 0; mi < 2; mi++) {
        int row0 = mbase + wm * 32 + mi * 16 + qr;
#pragma unroll
        for (int ni = 0; ni < 8; ni++) {
            int col = nbase + wn * 64 + ni * 8 + 2 * qc;
            float bx = bias[col], by = bias[col + 1];
            float2 v0 = make_float2(acc[mi][ni][0] + bx, acc[mi][ni][1] + by);
            float2 v1 = make_float2(acc[mi][ni][2] + bx, acc[mi][ni][3] + by);
            *(float2*)(out + (size_t)row0 * FEAT + col)       = v0;
            *(float2*)(out + (size_t)(row0 + 8) * FEAT + col) = v1;
        }
    }
}

// ============================================================================
// Kernel 3: grouped LoRA. 2 CTAs per adapter (token-parity split).
//   out[n] += (x[n] . A[id]) . B[id]
// ============================================================================
static constexpr int APAD = 17;                    // bank-conflict-free stride
static constexpr int LORA_A_FLOATS = DIM * APAD;   // 17408
static constexpr int LORA_SMEM =
    LORA_A_FLOATS * 4 + 16 * FEAT * 4 + 1024 * 4 + 8 * 16 * 4 + 64;

__global__ void __launch_bounds__(256, 1)
lora_kernel(const float* __restrict__ x, const int* __restrict__ ids,
            const float* __restrict__ lora_a, const float* __restrict__ lora_b,
            float* __restrict__ out) {
    extern __shared__ char dsm[];
    float* A_s  = (float*)dsm;                     // [DIM][APAD]
    float* B_s  = A_s + LORA_A_FLOATS;             // [16][FEAT]
    int*   list = (int*)(B_s + 16 * FEAT);         // [1024]
    float* rv_s = (float*)(list + 1024);           // [8][16]
    int*   cnt  = (int*)(rv_s + 8 * 16);

    const int tid  = threadIdx.x;
    const int warp = tid >> 5, lane = tid & 31;
    const int slot = blockIdx.x >> 1;
    const int sub  = blockIdx.x & 1;

    if (tid == 0) *cnt = 0;

    {   // load A[slot] (1024x16) into padded SMEM
        const float4* ap = (const float4*)(lora_a + (size_t)slot * DIM * 16);
        for (int i = tid; i < DIM * 16 / 4; i += 256) {
            float4 v = ap[i];
            int d = i >> 2, r = (i & 3) * 4;
            float* drow = &A_s[d * APAD + r];
            drow[0] = v.x; drow[1] = v.y; drow[2] = v.z; drow[3] = v.w;
        }
    }
    {   // load B[slot] (16x1024)
        const float4* bp = (const float4*)(lora_b + (size_t)slot * 16 * FEAT);
        float4* bs = (float4*)B_s;
        for (int i = tid; i < 16 * FEAT / 4; i += 256) bs[i] = bp[i];
    }
    __syncthreads();

    for (int m = tid; m < N_TOK / 2; m += 256) {
        int n = sub + 2 * m;
        if (ids[n] == slot) {
            int p = atomicAdd(cnt, 1);
            if (p < 1024) list[p] = n;
        }
    }
    __syncthreads();
    int total = min(*cnt, 1024);

    for (int i = warp; i < total; i += 8) {
        int n = list[i];
        const float* xr = x + (size_t)n * DIM;

        float accr[16];
#pragma unroll
        for (int r = 0; r < 16; r++) accr[r] = 0.f;
        for (int kk = 0; kk < 32; kk++) {
            int d = kk * 32 + lane;
            float xv = xr[d];
            const float* ar = &A_s[d * APAD];
#pragma unroll
            for (int r = 0; r < 16; r++) accr[r] = fmaf(xv, ar[r], accr[r]);
        }
#pragma unroll
        for (int r = 0; r < 16; r++) {
            float v = accr[r];
#pragma unroll
            for (int o = 16; o > 0; o >>= 1) v += __shfl_xor_sync(0xFFFFFFFFu, v, o);
            if (lane == 0) rv_s[warp * 16 + r] = v;
        }
        __syncwarp();
        float rv[16];
#pragma unroll
        for (int r = 0; r < 16; r++) rv[r] = rv_s[warp * 16 + r];
        __syncwarp();

        float* orow = out + (size_t)n * FEAT;
        for (int kk = 0; kk < 32; kk++) {
            int f = kk * 32 + lane;
            float a = 0.f;
#pragma unroll
            for (int r = 0; r < 16; r++) a = fmaf(rv[r], B_s[r * FEAT + f], a);
            orow[f] += a;
        }
    }
}

// ============================================================================
// Launch
// ============================================================================
extern "C" void kernel_launch(void* const* d_in, const int* in_sizes, int n_in,
                              void* d_out, int out_size) {
    const float* x      = (const float*)d_in[0];
    const int*   ids    = (const int*)d_in[1];
    const float* W      = (const float*)d_in[2];
    const float* bias   = (const float*)d_in[3];
    const float* lora_a = (const float*)d_in[4];
    const float* lora_b = (const float*)d_in[5];
    float* out = (float*)d_out;

    cudaFuncSetAttribute(gemm_tf32_kernel,
                         cudaFuncAttributeMaxDynamicSharedMemorySize, GEMM_SMEM);
    cudaFuncSetAttribute(lora_kernel,
                         cudaFuncAttributeMaxDynamicSharedMemorySize, LORA_SMEM);

    dim3 tgrid(FEAT / 32, DIM / 32);
    transpose_w_kernel<<<tgrid, dim3(32, 8)>>>(W);

    dim3 ggrid(N_TOK / BM, FEAT / BN);   // 32 x 8
    gemm_tf32_kernel<<<ggrid, 512, GEMM_SMEM>>>(x, bias, out);

    lora_kernel<<<128, 256, LORA_SMEM>>>(x, ids, lora_a, lora_b, out);
}

// round 5
// speedup vs baseline: 1.0444x; 1.0444x over previous
#include <cuda_runtime.h>
#include <cstdint>

// ============================================================================
// LoRADense: out = x @ W + bias + (x . A[id]) . B[id]
//   x: (8192,1024) f32   adapter_ids: (8192,) i32   W: (1024,1024) f32
//   bias: (1024,) f32    lora_a: (64,1024,16) f32   lora_b: (64,16,1024) f32
//
// R5: fix register-cap spill (512thr -> 256thr, warp tile 64x64).
//   1) transpose W -> g_wt (F,D), tf32 rna-rounded
//   2) tf32 GEMM mma.sync m16n8k8: BM=256 BN=128 BK=32, 3-stage cp.async,
//      256 threads, 8 warps (4x2), 64x64 warp tile, no spills
//   3) grouped LoRA: 2 CTAs per adapter, A/B in SMEM, warp-per-token RMW
// ============================================================================

#define N_TOK 8192
#define DIM   1024
#define FEAT  1024

__device__ float g_wt[FEAT * DIM];   // W^T, tf32-rounded (4 MB scratch)

__device__ __forceinline__ uint32_t to_tf32(float v) {
    uint32_t o;
    asm("cvt.rna.tf32.f32 %0, %1;" : "=r"(o) : "f"(v));
    return o;
}
__device__ __forceinline__ void cp16(uint32_t dst, const void* src) {
    asm volatile("cp.async.cg.shared.global [%0], [%1], 16;" :: "r"(dst), "l"(src));
}
__device__ __forceinline__ uint32_t smem_u32(const void* p) {
    uint32_t a;
    asm("{ .reg .u64 t; cvta.to.shared.u64 t, %1; cvt.u32.u64 %0, t; }"
        : "=r"(a) : "l"(p));
    return a;
}
__device__ __forceinline__ void mma_tf32(float& c0, float& c1, float& c2, float& c3,
                                         uint32_t a0, uint32_t a1, uint32_t a2, uint32_t a3,
                                         uint32_t b0, uint32_t b1) {
    asm volatile(
        "mma.sync.aligned.m16n8k8.row.col.f32.tf32.tf32.f32 "
        "{%0,%1,%2,%3}, {%4,%5,%6,%7}, {%8,%9}, {%0,%1,%2,%3};"
        : "+f"(c0), "+f"(c1), "+f"(c2), "+f"(c3)
        : "r"(a0), "r"(a1), "r"(a2), "r"(a3), "r"(b0), "r"(b1));
}

// ============================================================================
// Kernel 1: W (D,F) -> g_wt (F,D), tf32-rounded
// ============================================================================
__global__ void transpose_w_kernel(const float* __restrict__ W) {
    __shared__ float t[32][33];
    int fx = blockIdx.x * 32 + threadIdx.x;
    int dy = blockIdx.y * 32 + threadIdx.y;
#pragma unroll
    for (int i = 0; i < 32; i += 8)
        t[threadIdx.y + i][threadIdx.x] = W[(size_t)(dy + i) * FEAT + fx];
    __syncthreads();
    int dx = blockIdx.y * 32 + threadIdx.x;
    int fy = blockIdx.x * 32 + threadIdx.y;
#pragma unroll
    for (int i = 0; i < 32; i += 8)
        g_wt[(size_t)(fy + i) * DIM + dx] =
            __uint_as_float(to_tf32(t[threadIdx.x][threadIdx.y + i]));
}

// ============================================================================
// Kernel 2: tf32 GEMM, BM=256 BN=128 BK=32, 256 thr, warp tile 64x64
// ============================================================================
static constexpr int BM = 256, BN = 128, BK = 32;
static constexpr int AS = 36;                     // padded row stride (floats)
static constexpr int NKCH = DIM / BK;             // 32
static constexpr int DEPTH = 3;
static constexpr int A_FLOATS = BM * AS;          // 9216
static constexpr int B_FLOATS = BN * AS;          // 4608
static constexpr int STAGE_FLOATS = A_FLOATS + B_FLOATS;
static constexpr int GEMM_SMEM = DEPTH * STAGE_FLOATS * 4;   // 165888 B

__device__ __forceinline__ void load_stage(uint32_t sb, int slot, int kc,
                                           const float* __restrict__ x,
                                           int mbase, int nbase, int tid) {
    uint32_t baseA = sb + (uint32_t)(slot * STAGE_FLOATS) * 4u;
    uint32_t baseB = baseA + (uint32_t)A_FLOATS * 4u;
    const float* xp = x    + (size_t)mbase * DIM + kc * BK;
    const float* wp = g_wt + (size_t)nbase * DIM + kc * BK;
    // A: 256 rows x 8 16B-chunks = 2048 chunks, 8 per thread
#pragma unroll
    for (int it = 0; it < 8; it++) {
        int c  = tid + it * 256;
        int r  = c >> 3, cc = c & 7;
        cp16(baseA + (uint32_t)(r * AS + cc * 4) * 4u, xp + (size_t)r * DIM + cc * 4);
    }
    // B: 128 rows x 8 chunks = 1024 chunks, 4 per thread
#pragma unroll
    for (int it = 0; it < 4; it++) {
        int c  = tid + it * 256;
        int r  = c >> 3, cc = c & 7;
        cp16(baseB + (uint32_t)(r * AS + cc * 4) * 4u, wp + (size_t)r * DIM + cc * 4);
    }
}

__global__ void __launch_bounds__(256, 1)
gemm_tf32_kernel(const float* __restrict__ x, const float* __restrict__ bias,
                 float* __restrict__ out) {
    extern __shared__ float smem[];
    uint32_t sb = smem_u32(smem);

    const int tid = threadIdx.x;
    const int wid = tid >> 5, lane = tid & 31;
    const int wm = wid >> 1, wn = wid & 1;     // 4 x 2 warp grid, 64x64 tiles
    const int qr = lane >> 2, qc = lane & 3;
    const int mbase = blockIdx.x * BM;
    const int nbase = blockIdx.y * BN;

    float acc[4][8][4];
#pragma unroll
    for (int mi = 0; mi < 4; mi++)
#pragma unroll
        for (int ni = 0; ni < 8; ni++)
#pragma unroll
            for (int q = 0; q < 4; q++) acc[mi][ni][q] = 0.f;

    // prologue: chunks 0,1 -> slots 0,1
    load_stage(sb, 0, 0, x, mbase, nbase, tid);
    asm volatile("cp.async.commit_group;" ::: "memory");
    load_stage(sb, 1, 1, x, mbase, nbase, tid);
    asm volatile("cp.async.commit_group;" ::: "memory");

#pragma unroll 1
    for (int i = 0; i < NKCH; i++) {
        if (i >= NKCH - 1) asm volatile("cp.async.wait_group 0;" ::: "memory");
        else               asm volatile("cp.async.wait_group 1;" ::: "memory");
        __syncthreads();   // chunk i landed; all warps done with chunk i-1

        if (i + 2 < NKCH) {
            load_stage(sb, (i + 2) % DEPTH, i + 2, x, mbase, nbase, tid);
            asm volatile("cp.async.commit_group;" ::: "memory");
        }

        const int slot = i % DEPTH;
        const uint32_t* As = (const uint32_t*)(smem + slot * STAGE_FLOATS);
        const uint32_t* Bs = As + A_FLOATS;

#pragma unroll
        for (int ks = 0; ks < 4; ks++) {
            const int kb = ks * 8;
            uint32_t a[4][4];
#pragma unroll
            for (int mi = 0; mi < 4; mi++) {
                int row = wm * 64 + mi * 16 + qr;
                a[mi][0] = As[row * AS + kb + qc];
                a[mi][1] = As[(row + 8) * AS + kb + qc];
                a[mi][2] = As[row * AS + kb + qc + 4];
                a[mi][3] = As[(row + 8) * AS + kb + qc + 4];
            }
            uint32_t b[8][2];
#pragma unroll
            for (int ni = 0; ni < 8; ni++) {
                int col = wn * 64 + ni * 8 + qr;
                b[ni][0] = Bs[col * AS + kb + qc];
                b[ni][1] = Bs[col * AS + kb + qc + 4];
            }
#pragma unroll
            for (int mi = 0; mi < 4; mi++)
#pragma unroll
                for (int ni = 0; ni < 8; ni++)
                    mma_tf32(acc[mi][ni][0], acc[mi][ni][1],
                             acc[mi][ni][2], acc[mi][ni][3],
                             a[mi][0], a[mi][1], a[mi][2], a[mi][3],
                             b[ni][0], b[ni][1]);
        }
    }

    // epilogue: out = acc + bias
#pragma unroll
    for (int mi = 0; mi < 4; mi++) {
        int row0 = mbase + wm * 64 + mi * 16 + qr;
#pragma unroll
        for (int ni = 0; ni < 8; ni++) {
            int col = nbase + wn * 64 + ni * 8 + 2 * qc;
            float bx = bias[col], by = bias[col + 1];
            float2 v0 = make_float2(acc[mi][ni][0] + bx, acc[mi][ni][1] + by);
            float2 v1 = make_float2(acc[mi][ni][2] + bx, acc[mi][ni][3] + by);
            *(float2*)(out + (size_t)row0 * FEAT + col)       = v0;
            *(float2*)(out + (size_t)(row0 + 8) * FEAT + col) = v1;
        }
    }
}

// ============================================================================
// Kernel 3: grouped LoRA. 2 CTAs per adapter (token-parity split).
// ============================================================================
static constexpr int APAD = 17;
static constexpr int LORA_A_FLOATS = DIM * APAD;   // 17408
static constexpr int LORA_SMEM =
    LORA_A_FLOATS * 4 + 16 * FEAT * 4 + 1024 * 4 + 8 * 16 * 4 + 64;

__global__ void __launch_bounds__(256, 1)
lora_kernel(const float* __restrict__ x, const int* __restrict__ ids,
            const float* __restrict__ lora_a, const float* __restrict__ lora_b,
            float* __restrict__ out) {
    extern __shared__ char dsm[];
    float* A_s  = (float*)dsm;                     // [DIM][APAD]
    float* B_s  = A_s + LORA_A_FLOATS;             // [16][FEAT]
    int*   list = (int*)(B_s + 16 * FEAT);         // [1024]
    float* rv_s = (float*)(list + 1024);           // [8][16]
    int*   cnt  = (int*)(rv_s + 8 * 16);

    const int tid  = threadIdx.x;
    const int warp = tid >> 5, lane = tid & 31;
    const int slot = blockIdx.x >> 1;
    const int sub  = blockIdx.x & 1;

    if (tid == 0) *cnt = 0;

    {   // load A[slot] (1024x16) into padded SMEM
        const float4* ap = (const float4*)(lora_a + (size_t)slot * DIM * 16);
        for (int i = tid; i < DIM * 16 / 4; i += 256) {
            float4 v = ap[i];
            int d = i >> 2, r = (i & 3) * 4;
            float* drow = &A_s[d * APAD + r];
            drow[0] = v.x; drow[1] = v.y; drow[2] = v.z; drow[3] = v.w;
        }
    }
    {   // load B[slot] (16x1024)
        const float4* bp = (const float4*)(lora_b + (size_t)slot * 16 * FEAT);
        float4* bs = (float4*)B_s;
        for (int i = tid; i < 16 * FEAT / 4; i += 256) bs[i] = bp[i];
    }
    __syncthreads();

    for (int m = tid; m < N_TOK / 2; m += 256) {
        int n = sub + 2 * m;
        if (ids[n] == slot) {
            int p = atomicAdd(cnt, 1);
            if (p < 1024) list[p] = n;
        }
    }
    __syncthreads();
    int total = min(*cnt, 1024);

    for (int i = warp; i < total; i += 8) {
        int n = list[i];
        const float* xr = x + (size_t)n * DIM;

        float accr[16];
#pragma unroll
        for (int r = 0; r < 16; r++) accr[r] = 0.f;
        for (int kk = 0; kk < 32; kk++) {
            int d = kk * 32 + lane;
            float xv = xr[d];
            const float* ar = &A_s[d * APAD];
#pragma unroll
            for (int r = 0; r < 16; r++) accr[r] = fmaf(xv, ar[r], accr[r]);
        }
#pragma unroll
        for (int r = 0; r < 16; r++) {
            float v = accr[r];
#pragma unroll
            for (int o = 16; o > 0; o >>= 1) v += __shfl_xor_sync(0xFFFFFFFFu, v, o);
            if (lane == 0) rv_s[warp * 16 + r] = v;
        }
        __syncwarp();
        float rv[16];
#pragma unroll
        for (int r = 0; r < 16; r++) rv[r] = rv_s[warp * 16 + r];
        __syncwarp();

        float* orow = out + (size_t)n * FEAT;
        for (int kk = 0; kk < 32; kk++) {
            int f = kk * 32 + lane;
            float a = 0.f;
#pragma unroll
            for (int r = 0; r < 16; r++) a = fmaf(rv[r], B_s[r * FEAT + f], a);
            orow[f] += a;
        }
    }
}

// ============================================================================
// Launch
// ============================================================================
extern "C" void kernel_launch(void* const* d_in, const int* in_sizes, int n_in,
                              void* d_out, int out_size) {
    const float* x      = (const float*)d_in[0];
    const int*   ids    = (const int*)d_in[1];
    const float* W      = (const float*)d_in[2];
    const float* bias   = (const float*)d_in[3];
    const float* lora_a = (const float*)d_in[4];
    const float* lora_b = (const float*)d_in[5];
    float* out = (float*)d_out;

    cudaFuncSetAttribute(gemm_tf32_kernel,
                         cudaFuncAttributeMaxDynamicSharedMemorySize, GEMM_SMEM);
    cudaFuncSetAttribute(lora_kernel,
                         cudaFuncAttributeMaxDynamicSharedMemorySize, LORA_SMEM);

    dim3 tgrid(FEAT / 32, DIM / 32);
    transpose_w_kernel<<<tgrid, dim3(32, 8)>>>(W);

    dim3 ggrid(N_TOK / BM, FEAT / BN);   // 32 x 8
    gemm_tf32_kernel<<<ggrid, 256, GEMM_SMEM>>>(x, bias, out);

    lora_kernel<<<128, 256, LORA_SMEM>>>(x, ids, lora_a, lora_b, out);
}